// round 11
// baseline (speedup 1.0000x reference)
#include <cuda_runtime.h>
#include <cuda_bf16.h>
#include <math.h>
#include <stdint.h>

#define N_A 50000
#define N_B 50000
#define NT  100000
#define NE  800000
#define EHN 1600000
#define CC  128

// ---------------- device scratch (static, no allocation) ----------------
__device__ float g_agg [NT * 8];
__device__ float g_hid [2 * NT * 64];
__device__ float g_lin [NT * CC];          // fp32 (GEMM self-term input)
__device__ __nv_bfloat16 g_lin16[NT * CC]; // bf16 shadow (gather input)
__device__ float g_m   [NT * CC];
__device__ float g_cur [NT * CC];
__device__ int   g_cnt [NT];               // [cntA | cntB]; reused as fill positions
__device__ int   g_offA[N_A + 1];
__device__ int   g_offB[N_B + 1];
__device__ int   g_csrAB[NE];              // src(A) ids grouped by dst(B)
__device__ int   g_csrBA[NE];              // src(B) ids grouped by dst(A)
__device__ float g_Wc   [2 * 64 * 128];
__device__ float g_bc   [2 * 128];
__device__ float g_WTpe  [2 * 128 * 192];
__device__ float g_WTsage[4 * 128 * 256];

// ---------------- helpers ----------------
__device__ __forceinline__ uint32_t smem_u32(const void* p) {
    uint32_t a;
    asm("{ .reg .u64 t; cvta.to.shared.u64 t, %1; cvt.u32.u64 %0, t; }" : "=r"(a) : "l"(p));
    return a;
}

__device__ __forceinline__ uint32_t cvt_tf32(float f) {
    uint32_t r;
    asm("cvt.rna.tf32.f32 %0, %1;" : "=r"(r) : "f"(f));
    return r;
}

__device__ __forceinline__ void mma_tf32(float c[4], const uint32_t a[4],
                                         uint32_t b0, uint32_t b1) {
    asm volatile(
        "mma.sync.aligned.m16n8k8.row.col.f32.tf32.tf32.f32 "
        "{%0,%1,%2,%3}, {%4,%5,%6,%7}, {%8,%9}, {%0,%1,%2,%3};"
        : "+f"(c[0]), "+f"(c[1]), "+f"(c[2]), "+f"(c[3])
        : "r"(a[0]), "r"(a[1]), "r"(a[2]), "r"(a[3]), "r"(b0), "r"(b1));
}

__device__ __forceinline__ void cpasync16(uint32_t daddr, const float* g, bool pred) {
    int sz = pred ? 16 : 0;
    asm volatile("cp.async.cg.shared.global [%0], [%1], 16, %2;"
                 :: "r"(daddr), "l"(g), "r"(sz) : "memory");
}
#define CP_COMMIT() asm volatile("cp.async.commit_group;" ::: "memory")

__device__ __forceinline__ void red4(float* addr, float4 v) {
    asm volatile("red.global.add.v4.f32 [%0], {%1,%2,%3,%4};"
                 :: "l"(addr), "f"(v.x), "f"(v.y), "f"(v.z), "f"(v.w) : "memory");
}

// ---------------- graph preprocessing (merged two-direction kernels) ----------------
__global__ void count2(const int* __restrict__ dstAB, const int* __restrict__ dstBA,
                       int* __restrict__ cntB, int* __restrict__ cntA) {
    int e = blockIdx.x * blockDim.x + threadIdx.x;
    if (e < NE)            atomicAdd(&cntB[dstAB[e]], 1);
    else if (e < 2 * NE)   atomicAdd(&cntA[dstBA[e - NE]], 1);
}

__global__ void scan2(int* __restrict__ cntA, int* __restrict__ offA,
                      int* __restrict__ cntB, int* __restrict__ offB) {
    __shared__ int part[1024];
    int* cnt = blockIdx.x ? cntB : cntA;
    int* off = blockIdx.x ? offB : offA;
    const int N = N_A;                      // N_A == N_B
    int tid = threadIdx.x;
    int chunk = (N + 1023) >> 10;
    int start = tid * chunk;
    int end = min(start + chunk, N);
    int s = 0;
    for (int i = start; i < end; i++) s += cnt[i];
    part[tid] = s;
    __syncthreads();
    for (int o = 1; o < 1024; o <<= 1) {
        int t = (tid >= o) ? part[tid - o] : 0;
        __syncthreads();
        part[tid] += t;
        __syncthreads();
    }
    int pre = part[tid] - s;
    for (int i = start; i < end; i++) {
        int c = cnt[i];
        off[i] = pre;
        cnt[i] = pre;                       // becomes running fill position
        pre += c;
    }
    if (tid == 1023) off[N] = part[1023];
}

__global__ void fill2(const int* __restrict__ srcAB, const int* __restrict__ dstAB,
                      const int* __restrict__ srcBA, const int* __restrict__ dstBA,
                      int* __restrict__ posB, int* __restrict__ posA,
                      int* __restrict__ csrAB, int* __restrict__ csrBA) {
    int e = blockIdx.x * blockDim.x + threadIdx.x;
    if (e < NE) {
        int p = atomicAdd(&posB[dstAB[e]], 1);
        csrAB[p] = srcAB[e];
    } else if (e < 2 * NE) {
        int i = e - NE;
        int p = atomicAdd(&posA[dstBA[i]], 1);
        csrBA[p] = srcBA[i];
    }
}

__global__ void agg_scatter(const float* __restrict__ PE, const int* __restrict__ hsrc,
                            const int* __restrict__ hdst, float* __restrict__ agg, int E) {
    int e = blockIdx.x * blockDim.x + threadIdx.x;
    if (e >= E) return;
    int s = hsrc[e], d = hdst[e];
    float4 v0 = *(const float4*)(PE + (size_t)s * 8);
    float4 v1 = *(const float4*)(PE + (size_t)s * 8 + 4);
    red4(agg + (size_t)d * 8,     v0);
    red4(agg + (size_t)d * 8 + 4, v1);
}

__global__ void fold_w(const float* __restrict__ W2, const float* __restrict__ peWpe,
                       float* __restrict__ Wc) {
    int idx = blockIdx.x * blockDim.x + threadIdx.x;
    if (idx >= 64 * 128) return;
    int i = idx >> 7, j = idx & 127;
    float s = 0.0f;
    #pragma unroll 8
    for (int p = 0; p < 64; p++) s += W2[i * 64 + p] * peWpe[p * 128 + j];
    Wc[idx] = s;
}

__global__ void fold_b(const float* __restrict__ b2, const float* __restrict__ peWpe,
                       const float* __restrict__ peb, float* __restrict__ bc) {
    int j = threadIdx.x;
    float s = peb[j];
    #pragma unroll 8
    for (int p = 0; p < 64; p++) s += b2[p] * peWpe[p * 128 + j];
    bc[j] = s;
}

// WT[n][kp(k)] = tf32_round( k < Kl ? Wl[k][n] : Wr[k-Kl][n] )
// K-interleave within each 8-group: logical pair (k, k+4) lands physically adjacent,
// so the mma B-fragment (b0=k, b1=k+4) becomes a single LDS.64.
__global__ void transpose_pack(const float* __restrict__ Wl, const float* __restrict__ Wr,
                               float* __restrict__ WT, int Kl, int Kr) {
    int K = Kl + Kr;
    int idx = blockIdx.x * blockDim.x + threadIdx.x;
    if (idx >= 128 * K) return;
    int n = idx / K, k = idx % K;
    float w = (k < Kl) ? Wl[(size_t)k * 128 + n] : Wr[(size_t)(k - Kl) * 128 + n];
    int kp = (k & ~7) | ((k & 3) * 2) | ((k >> 2) & 1);
    WT[(size_t)n * K + kp] = __uint_as_float(cvt_tf32(w));
}

__global__ void hid_kernel2(const float* __restrict__ agg,
                            const float* __restrict__ W1, const float* __restrict__ b1,
                            float* __restrict__ hid, int NTn) {
    __shared__ float sW1[2][512];
    __shared__ float sb1[2][64];
    int tid = threadIdx.x;
    for (int i = tid; i < 512; i += 256) { sW1[0][i] = W1[i]; sW1[1][i] = W1[512 + i]; }
    if (tid < 64) { sb1[0][tid] = b1[tid]; sb1[1][tid] = b1[64 + tid]; }
    __syncthreads();
    int r = tid >> 6, j = tid & 63;
    int row = blockIdx.x * 4 + r;
    if (row < NTn) {
        float a[8];
        #pragma unroll
        for (int k = 0; k < 8; k++) a[k] = agg[(size_t)row * 8 + k];
        #pragma unroll
        for (int l = 0; l < 2; l++) {
            float h = sb1[l][j];
            #pragma unroll
            for (int k = 0; k < 8; k++) h += a[k] * sW1[l][k * 64 + j];
            hid[(size_t)l * NT * 64 + (size_t)row * 64 + j] = fmaxf(h, 0.0f);
        }
    }
}

// ---------------- merged CSR mean gather (bf16 source): one warp per dst row ----------------
__global__ void mean_gather2(const __nv_bfloat16* __restrict__ lin16,
                             const int* __restrict__ csrBA, const int* __restrict__ offA,
                             const int* __restrict__ csrAB, const int* __restrict__ offB,
                             float* __restrict__ m)
{
    int w = (blockIdx.x * blockDim.x + threadIdx.x) >> 5;
    if (w >= NT) return;
    int lane = threadIdx.x & 31;
    const int* csr; const int* off; int srcBase, r;
    if (w < N_A) { csr = csrBA; off = offA; srcBase = N_A; r = w; }
    else         { csr = csrAB; off = offB; srcBase = 0;   r = w - N_A; }
    int s0 = off[r], s1 = off[r + 1];
    float4 acc = make_float4(0.f, 0.f, 0.f, 0.f);
    int i = s0;
    for (; i + 4 <= s1; i += 4) {
        int i0 = __ldg(csr + i),     i1 = __ldg(csr + i + 1);
        int i2 = __ldg(csr + i + 2), i3 = __ldg(csr + i + 3);
        #pragma unroll
        for (int u = 0; u < 4; u++) {
            int sidx = (u == 0) ? i0 : (u == 1) ? i1 : (u == 2) ? i2 : i3;
            uint2 pk = *(const uint2*)(lin16 + (size_t)(srcBase + sidx) * CC + lane * 4);
            __nv_bfloat162 h0 = *(__nv_bfloat162*)&pk.x;
            __nv_bfloat162 h1 = *(__nv_bfloat162*)&pk.y;
            float2 f0 = __bfloat1622float2(h0);
            float2 f1 = __bfloat1622float2(h1);
            acc.x += f0.x; acc.y += f0.y; acc.z += f1.x; acc.w += f1.y;
        }
    }
    for (; i < s1; i++) {
        int sidx = __ldg(csr + i);
        uint2 pk = *(const uint2*)(lin16 + (size_t)(srcBase + sidx) * CC + lane * 4);
        __nv_bfloat162 h0 = *(__nv_bfloat162*)&pk.x;
        __nv_bfloat162 h1 = *(__nv_bfloat162*)&pk.y;
        float2 f0 = __bfloat1622float2(h0);
        float2 f1 = __bfloat1622float2(h1);
        acc.x += f0.x; acc.y += f0.y; acc.z += f1.x; acc.w += f1.y;
    }
    float sc = 1.0f / (float)max(s1 - s0, 1);
    acc.x *= sc; acc.y *= sc; acc.z *= sc; acc.w *= sc;
    *(float4*)(m + (size_t)w * CC + lane * 4) = acc;
}

// ---------------- tf32 mma.sync GEMM: 4-stage cp.async pipeline, merged A/B launch --------
#define TILE_F 2560
#define STAGES 4
#define GEMM_SMEM_F (640 + STAGES * 2 * TILE_F)

__device__ __forceinline__ void load_tile(
    const float* __restrict__ X0, int K0, const float* __restrict__ X1, int K1,
    const float* __restrict__ WT, int K, int m0, int M, int t,
    uint32_t asAddr, uint32_t bsAddr, int tid)
{
    int kb = t * 16;
    #pragma unroll
    for (int i = 0; i < 2; i++) {
        int f = i * 256 + tid;
        int row = f >> 2, q = f & 3;
        int kk = kb + q * 4;
        bool pred = (m0 + row) < M;
        const float* src = (kk < K0)
            ? X0 + (size_t)(m0 + row) * K0 + kk
            : X1 + (size_t)(m0 + row) * K1 + (kk - K0);
        cpasync16(asAddr + (uint32_t)(row * 20 + q * 4) * 4, src, pred);
    }
    #pragma unroll
    for (int i = 0; i < 2; i++) {
        int f = i * 256 + tid;
        int n = f >> 2, q = f & 3;
        cpasync16(bsAddr + (uint32_t)(n * 20 + q * 4) * 4,
                  WT + (size_t)n * K + kb + q * 4, true);
    }
    CP_COMMIT();
}

template<bool DO_LN>
__global__ void __launch_bounds__(256, 2)
gemm_mma(const float* X0a, const float* X0b, int K0,
         const float* X1a, const float* X1b, int K1,
         const float* WTa, const float* WTb, int K,
         const float* biasA, const float* biasB,
         const float* gamA, const float* betA,
         const float* gamB, const float* betB,
         float* outA, float* outB, __nv_bfloat16* out16,
         int Ma, int Mb, int blocksA)
{
    extern __shared__ float sm[];
    float* s_bias  = sm;
    float* s_gamma = sm + 128;
    float* s_beta  = sm + 256;
    float* s_sum   = sm + 384;
    float* s_ss    = sm + 512;
    float* As      = sm + 640;
    float* Bs      = As + STAGES * TILE_F;

    bool isB = (int)blockIdx.x >= blocksA;
    const float* X0   = isB ? X0b  : X0a;
    const float* X1   = isB ? X1b  : X1a;
    const float* WT   = isB ? WTb  : WTa;
    const float* bias = isB ? biasB : biasA;
    const float* gamma = isB ? gamB : gamA;
    const float* beta  = isB ? betB : betA;
    float* out = isB ? outB : outA;
    int M  = isB ? Mb : Ma;
    int mrow0 = (isB ? ((int)blockIdx.x - blocksA) : (int)blockIdx.x) * 128;
    size_t row16base = isB ? (size_t)N_A : 0;

    int tid  = threadIdx.x;
    int lane = tid & 31;
    int warp = tid >> 5;
    int wm = warp & 3;
    int wn = warp >> 2;

    if (tid < 128) {
        s_bias[tid] = bias[tid];
        if (DO_LN) {
            s_gamma[tid] = gamma[tid];
            s_beta[tid]  = beta[tid];
            s_sum[tid] = 0.0f;
            s_ss[tid]  = 0.0f;
        }
    }

    uint32_t asAddr = smem_u32(As);
    uint32_t bsAddr = smem_u32(Bs);

    float c[2][8][4];
    #pragma unroll
    for (int mt = 0; mt < 2; mt++)
        #pragma unroll
        for (int nt = 0; nt < 8; nt++)
            #pragma unroll
            for (int j = 0; j < 4; j++) c[mt][nt][j] = 0.0f;

    const int T = K / 16;
    load_tile(X0, K0, X1, K1, WT, K, mrow0, M, 0, asAddr, bsAddr, tid);
    load_tile(X0, K0, X1, K1, WT, K, mrow0, M, 1,
              asAddr + TILE_F * 4, bsAddr + TILE_F * 4, tid);
    load_tile(X0, K0, X1, K1, WT, K, mrow0, M, 2,
              asAddr + 2 * TILE_F * 4, bsAddr + 2 * TILE_F * 4, tid);

    for (int t = 0; t < T; t++) {
        int rem = T - 1 - t;
        if (rem >= 2)      asm volatile("cp.async.wait_group 2;" ::: "memory");
        else if (rem == 1) asm volatile("cp.async.wait_group 1;" ::: "memory");
        else               asm volatile("cp.async.wait_group 0;" ::: "memory");
        __syncthreads();

        const float* Ab = As + (t & 3) * TILE_F;
        const float* Bb = Bs + (t & 3) * TILE_F;
        #pragma unroll
        for (int ks = 0; ks < 2; ks++) {
            int k0 = ks * 8 + (lane & 3);           // logical k (A side, natural layout)
            int kp = ks * 8 + 2 * (lane & 3);       // physical k (B side, interleaved)
            uint32_t a[2][4];
            #pragma unroll
            for (int mt = 0; mt < 2; mt++) {
                int rb = wm * 32 + mt * 16 + (lane >> 2);
                a[mt][0] = cvt_tf32(Ab[rb * 20 + k0]);
                a[mt][1] = cvt_tf32(Ab[(rb + 8) * 20 + k0]);
                a[mt][2] = cvt_tf32(Ab[rb * 20 + k0 + 4]);
                a[mt][3] = cvt_tf32(Ab[(rb + 8) * 20 + k0 + 4]);
            }
            #pragma unroll
            for (int nt = 0; nt < 8; nt++) {
                int nb = wn * 64 + nt * 8 + (lane >> 2);
                float2 bp = *(const float2*)(Bb + nb * 20 + kp);   // (b0=k0, b1=k0+4)
                uint32_t b0 = __float_as_uint(bp.x);
                uint32_t b1 = __float_as_uint(bp.y);
                mma_tf32(c[0][nt], a[0], b0, b1);
                mma_tf32(c[1][nt], a[1], b0, b1);
            }
        }
        // NOTE: no trailing __syncthreads needed with 4 stages — the buffer written
        // below ((t+3)&3) was last read at t-1, and the top-of-iteration barrier at t
        // already guaranteed all warps finished t-1.
        if (t + 3 < T)
            load_tile(X0, K0, X1, K1, WT, K, mrow0, M, t + 3,
                      asAddr + (uint32_t)((t + 3) & 3) * TILE_F * 4,
                      bsAddr + (uint32_t)((t + 3) & 3) * TILE_F * 4, tid);
    }

    // ---- add bias ----
    #pragma unroll
    for (int nt = 0; nt < 8; nt++) {
        int col = wn * 64 + nt * 8 + 2 * (lane & 3);
        float bx = s_bias[col], by = s_bias[col + 1];
        #pragma unroll
        for (int mt = 0; mt < 2; mt++) {
            c[mt][nt][0] += bx; c[mt][nt][1] += by;
            c[mt][nt][2] += bx; c[mt][nt][3] += by;
        }
    }

    if (!DO_LN) {
        #pragma unroll
        for (int mt = 0; mt < 2; mt++)
            #pragma unroll
            for (int h = 0; h < 2; h++) {
                int rloc = wm * 32 + mt * 16 + (lane >> 2) + h * 8;
                int row = mrow0 + rloc;
                if (row < M) {
                    #pragma unroll
                    for (int nt = 0; nt < 8; nt++) {
                        int col = wn * 64 + nt * 8 + 2 * (lane & 3);
                        float2 o = make_float2(c[mt][nt][h * 2], c[mt][nt][h * 2 + 1]);
                        *(float2*)(out + (size_t)row * 128 + col) = o;
                        __nv_bfloat162 o16 = __float22bfloat162_rn(o);
                        *(__nv_bfloat162*)(out16 + (row16base + row) * 128 + col) = o16;
                    }
                }
            }
        return;
    }

    // ---- LayerNorm + ReLU ----
    #pragma unroll
    for (int mt = 0; mt < 2; mt++)
        #pragma unroll
        for (int h = 0; h < 2; h++) {
            float s = 0.f, q = 0.f;
            #pragma unroll
            for (int nt = 0; nt < 8; nt++) {
                float v0 = c[mt][nt][h * 2], v1 = c[mt][nt][h * 2 + 1];
                s += v0 + v1;
                q += v0 * v0 + v1 * v1;
            }
            s += __shfl_xor_sync(0xffffffffu, s, 1);
            s += __shfl_xor_sync(0xffffffffu, s, 2);
            q += __shfl_xor_sync(0xffffffffu, q, 1);
            q += __shfl_xor_sync(0xffffffffu, q, 2);
            if ((lane & 3) == 0) {
                int rl = wm * 32 + mt * 16 + (lane >> 2) + h * 8;
                atomicAdd(&s_sum[rl], s);
                atomicAdd(&s_ss[rl], q);
            }
        }
    __syncthreads();
    #pragma unroll
    for (int mt = 0; mt < 2; mt++)
        #pragma unroll
        for (int h = 0; h < 2; h++) {
            int rl = wm * 32 + mt * 16 + (lane >> 2) + h * 8;
            int row = mrow0 + rl;
            float mu   = s_sum[rl] * (1.0f / 128.0f);
            float var  = s_ss[rl] * (1.0f / 128.0f) - mu * mu;
            float rstd = rsqrtf(var + 1e-5f);
            if (row < M) {
                #pragma unroll
                for (int nt = 0; nt < 8; nt++) {
                    int col = wn * 64 + nt * 8 + 2 * (lane & 3);
                    float2 o;
                    o.x = fmaxf((c[mt][nt][h * 2]     - mu) * rstd * s_gamma[col]     + s_beta[col],     0.f);
                    o.y = fmaxf((c[mt][nt][h * 2 + 1] - mu) * rstd * s_gamma[col + 1] + s_beta[col + 1], 0.f);
                    *(float2*)(out + (size_t)row * 128 + col) = o;
                }
            }
        }
}

// ---------------- launch ----------------
extern "C" void kernel_launch(void* const* d_in, const int* in_sizes, int n_in,
                              void* d_out, int out_size)
{
    const float* xA     = (const float*)d_in[0];
    const float* xB     = (const float*)d_in[1];
    const float* PE     = (const float*)d_in[2];
    const int*   edgeAB = (const int*)  d_in[3];
    const int*   edgeBA = (const int*)  d_in[4];
    const int*   hedge  = (const int*)  d_in[5];
    const float* sWl    = (const float*)d_in[6];
    const float* sbl    = (const float*)d_in[7];
    const float* sWr    = (const float*)d_in[8];
    const float* lng    = (const float*)d_in[9];
    const float* lnb    = (const float*)d_in[10];
    const float* pW1    = (const float*)d_in[11];
    const float* pb1    = (const float*)d_in[12];
    const float* pW2    = (const float*)d_in[13];
    const float* pb2    = (const float*)d_in[14];
    const float* peW    = (const float*)d_in[15];
    const float* peb    = (const float*)d_in[16];
    float* out = (float*)d_out;

    float *agg, *hid, *lin, *m, *cur, *Wc, *bc, *WTpe, *WTsage;
    __nv_bfloat16* lin16;
    int *cnt, *offA, *offB, *csrAB, *csrBA;
    cudaGetSymbolAddress((void**)&agg,    g_agg);
    cudaGetSymbolAddress((void**)&hid,    g_hid);
    cudaGetSymbolAddress((void**)&lin,    g_lin);
    cudaGetSymbolAddress((void**)&lin16,  g_lin16);
    cudaGetSymbolAddress((void**)&m,      g_m);
    cudaGetSymbolAddress((void**)&cur,    g_cur);
    cudaGetSymbolAddress((void**)&cnt,    g_cnt);
    cudaGetSymbolAddress((void**)&offA,   g_offA);
    cudaGetSymbolAddress((void**)&offB,   g_offB);
    cudaGetSymbolAddress((void**)&csrAB,  g_csrAB);
    cudaGetSymbolAddress((void**)&csrBA,  g_csrBA);
    cudaGetSymbolAddress((void**)&Wc,     g_Wc);
    cudaGetSymbolAddress((void**)&bc,     g_bc);
    cudaGetSymbolAddress((void**)&WTpe,   g_WTpe);
    cudaGetSymbolAddress((void**)&WTsage, g_WTsage);
    int* cntA = cnt;
    int* cntB = cnt + N_A;

    size_t gsm = GEMM_SMEM_F * sizeof(float);   // 84480 B (>48KB)
    cudaFuncSetAttribute(gemm_mma<false>, cudaFuncAttributeMaxDynamicSharedMemorySize, (int)gsm);
    cudaFuncSetAttribute(gemm_mma<true>,  cudaFuncAttributeMaxDynamicSharedMemorySize, (int)gsm);

    cudaStream_t s2;
    cudaStreamCreateWithFlags(&s2, cudaStreamNonBlocking);
    cudaEvent_t e0, e_wt, e_csr;
    cudaEventCreateWithFlags(&e0,    cudaEventDisableTiming);
    cudaEventCreateWithFlags(&e_wt,  cudaEventDisableTiming);
    cudaEventCreateWithFlags(&e_csr, cudaEventDisableTiming);

    cudaEventRecord(e0, 0);
    cudaStreamWaitEvent(s2, e0, 0);

    // ---- s2: weight folds + transposes, then compact CSR chain ----
    for (int l = 0; l < 2; l++) {
        const float* peWpe = peW + (size_t)l * 192 * 128 + 128 * 128;
        fold_w<<<32, 256, 0, s2>>>(pW2 + l * 4096, peWpe, Wc + (size_t)l * 64 * 128);
        fold_b<<<1, 128, 0, s2>>>(pb2 + l * 64, peWpe, peb + l * 128, bc + l * 128);
        transpose_pack<<<(128 * 192 + 255) / 256, 256, 0, s2>>>(
            peW + (size_t)l * 192 * 128, Wc + (size_t)l * 64 * 128,
            WTpe + (size_t)l * 128 * 192, 128, 64);
        for (int e = 0; e < 2; e++) {
            int li = l * 2 + e;
            transpose_pack<<<(128 * 256 + 255) / 256, 256, 0, s2>>>(
                sWl + (size_t)li * 16384, sWr + (size_t)li * 16384,
                WTsage + (size_t)li * 128 * 256, 128, 128);
        }
    }
    cudaEventRecord(e_wt, s2);

    cudaMemsetAsync(cnt, 0, NT * sizeof(int), s2);
    count2<<<(2 * NE + 255) / 256, 256, 0, s2>>>(edgeAB + NE, edgeBA + NE, cntB, cntA);
    scan2<<<2, 1024, 0, s2>>>(cntA, offA, cntB, offB);
    fill2<<<(2 * NE + 255) / 256, 256, 0, s2>>>(edgeAB, edgeAB + NE, edgeBA, edgeBA + NE,
                                                cntB, cntA, csrAB, csrBA);
    cudaEventRecord(e_csr, s2);

    // ---- default stream: critical path ----
    cudaMemcpyAsync(agg, PE, (size_t)NT * 8 * sizeof(float), cudaMemcpyDeviceToDevice);
    agg_scatter<<<(EHN + 255) / 256, 256>>>(PE, hedge, hedge + EHN, agg, EHN);
    hid_kernel2<<<(NT + 3) / 4, 256>>>(agg, pW1, pb1, hid, NT);

    cudaStreamWaitEvent(0, e_wt, 0);

    const float* srcA = xA;
    const float* srcB = xB;
    const int blocksA = (N_A + 127) / 128;
    dim3 gGrid(2 * blocksA);
    float* linB = lin + (size_t)N_A * CC;
    float* mB   = m   + (size_t)N_A * CC;
    bool joined_csr = false;

    for (int l = 0; l < 2; l++) {
        const float* hl = hid + (size_t)l * NT * 64;

        gemm_mma<false><<<gGrid, 256, gsm>>>(
            srcA, srcB, 128,
            hl, hl + (size_t)N_A * 64, 64,
            WTpe + (size_t)l * 128 * 192, WTpe + (size_t)l * 128 * 192, 192,
            bc + l * 128, bc + l * 128,
            nullptr, nullptr, nullptr, nullptr,
            lin, linB, lin16, N_A, N_B, blocksA);

        if (!joined_csr) { cudaStreamWaitEvent(0, e_csr, 0); joined_csr = true; }

        mean_gather2<<<(NT * 32 + 255) / 256, 256>>>(lin16, csrBA, offA,
                                                     csrAB, offB, m);

        float* outA = (l == 1) ? out                    : cur;
        float* outB = (l == 1) ? out + (size_t)N_A * CC : cur + (size_t)N_A * CC;

        gemm_mma<true><<<gGrid, 256, gsm>>>(
            m, mB, 128,
            lin, linB, 128,
            WTsage + (size_t)(l * 2 + 1) * 128 * 256,
            WTsage + (size_t)(l * 2 + 0) * 128 * 256, 256,
            sbl + (l * 2 + 1) * 128, sbl + (l * 2 + 0) * 128,
            lng + (l * 2 + 0) * 128, lnb + (l * 2 + 0) * 128,
            lng + (l * 2 + 1) * 128, lnb + (l * 2 + 1) * 128,
            outA, outB, nullptr, N_A, N_B, blocksA);

        srcA = cur;
        srcB = cur + (size_t)N_A * CC;
    }
}

// round 12
// speedup vs baseline: 1.1544x; 1.1544x over previous
#include <cuda_runtime.h>
#include <cuda_bf16.h>
#include <cuda_fp16.h>
#include <math.h>
#include <stdint.h>

#define N_A 50000
#define N_B 50000
#define NT  100000
#define NE  800000
#define EHN 1600000
#define CC  128

// ---------------- device scratch (static, no allocation) ----------------
__device__ float g_agg [NT * 8];
__device__ float g_hid [2 * NT * 64];
__device__ float g_lin [NT * CC];          // fp32 (GEMM self-term input)
__device__ __nv_bfloat16 g_lin16[NT * CC]; // bf16 shadow (gather input)
__device__ float g_m   [NT * CC];
__device__ float g_cur [NT * CC];
__device__ int   g_cnt [NT];               // [cntA | cntB]; reused as fill positions
__device__ int   g_offA[N_A + 1];
__device__ int   g_offB[N_B + 1];
__device__ int   g_csrAB[NE];              // src(A) ids grouped by dst(B)
__device__ int   g_csrBA[NE];              // src(B) ids grouped by dst(A)
__device__ float g_Wc   [2 * 64 * 128];
__device__ float g_bc   [2 * 128];
__device__ __half g_WTpe  [2 * 128 * 192];   // fp16 weights, [n][k]
__device__ __half g_WTsage[4 * 128 * 256];

// ---------------- helpers ----------------
__device__ __forceinline__ uint32_t smem_u32(const void* p) {
    uint32_t a;
    asm("{ .reg .u64 t; cvta.to.shared.u64 t, %1; cvt.u32.u64 %0, t; }" : "=r"(a) : "l"(p));
    return a;
}

__device__ __forceinline__ uint32_t pack_h2(float2 f) {
    __half2 h = __float22half2_rn(f);
    return *(uint32_t*)&h;
}

// fp16 HMMA m16n8k16, fp32 accumulate
__device__ __forceinline__ void mma_f16(float c[4], const uint32_t a[4],
                                        uint32_t b0, uint32_t b1) {
    asm volatile(
        "mma.sync.aligned.m16n8k16.row.col.f32.f16.f16.f32 "
        "{%0,%1,%2,%3}, {%4,%5,%6,%7}, {%8,%9}, {%0,%1,%2,%3};"
        : "+f"(c[0]), "+f"(c[1]), "+f"(c[2]), "+f"(c[3])
        : "r"(a[0]), "r"(a[1]), "r"(a[2]), "r"(a[3]), "r"(b0), "r"(b1));
}

__device__ __forceinline__ void cpasync16(uint32_t daddr, const void* g, bool pred) {
    int sz = pred ? 16 : 0;
    asm volatile("cp.async.cg.shared.global [%0], [%1], 16, %2;"
                 :: "r"(daddr), "l"(g), "r"(sz) : "memory");
}
#define CP_COMMIT() asm volatile("cp.async.commit_group;" ::: "memory")

__device__ __forceinline__ void red4(float* addr, float4 v) {
    asm volatile("red.global.add.v4.f32 [%0], {%1,%2,%3,%4};"
                 :: "l"(addr), "f"(v.x), "f"(v.y), "f"(v.z), "f"(v.w) : "memory");
}

// ---------------- graph preprocessing (merged two-direction kernels) ----------------
__global__ void count2(const int* __restrict__ dstAB, const int* __restrict__ dstBA,
                       int* __restrict__ cntB, int* __restrict__ cntA) {
    int e = blockIdx.x * blockDim.x + threadIdx.x;
    if (e < NE)            atomicAdd(&cntB[dstAB[e]], 1);
    else if (e < 2 * NE)   atomicAdd(&cntA[dstBA[e - NE]], 1);
}

__global__ void scan2(int* __restrict__ cntA, int* __restrict__ offA,
                      int* __restrict__ cntB, int* __restrict__ offB) {
    __shared__ int part[1024];
    int* cnt = blockIdx.x ? cntB : cntA;
    int* off = blockIdx.x ? offB : offA;
    const int N = N_A;                      // N_A == N_B
    int tid = threadIdx.x;
    int chunk = (N + 1023) >> 10;
    int start = tid * chunk;
    int end = min(start + chunk, N);
    int s = 0;
    for (int i = start; i < end; i++) s += cnt[i];
    part[tid] = s;
    __syncthreads();
    for (int o = 1; o < 1024; o <<= 1) {
        int t = (tid >= o) ? part[tid - o] : 0;
        __syncthreads();
        part[tid] += t;
        __syncthreads();
    }
    int pre = part[tid] - s;
    for (int i = start; i < end; i++) {
        int c = cnt[i];
        off[i] = pre;
        cnt[i] = pre;                       // becomes running fill position
        pre += c;
    }
    if (tid == 1023) off[N] = part[1023];
}

__global__ void fill2(const int* __restrict__ srcAB, const int* __restrict__ dstAB,
                      const int* __restrict__ srcBA, const int* __restrict__ dstBA,
                      int* __restrict__ posB, int* __restrict__ posA,
                      int* __restrict__ csrAB, int* __restrict__ csrBA) {
    int e = blockIdx.x * blockDim.x + threadIdx.x;
    if (e < NE) {
        int p = atomicAdd(&posB[dstAB[e]], 1);
        csrAB[p] = srcAB[e];
    } else if (e < 2 * NE) {
        int i = e - NE;
        int p = atomicAdd(&posA[dstBA[i]], 1);
        csrBA[p] = srcBA[i];
    }
}

__global__ void agg_scatter(const float* __restrict__ PE, const int* __restrict__ hsrc,
                            const int* __restrict__ hdst, float* __restrict__ agg, int E) {
    int e = blockIdx.x * blockDim.x + threadIdx.x;
    if (e >= E) return;
    int s = hsrc[e], d = hdst[e];
    float4 v0 = *(const float4*)(PE + (size_t)s * 8);
    float4 v1 = *(const float4*)(PE + (size_t)s * 8 + 4);
    red4(agg + (size_t)d * 8,     v0);
    red4(agg + (size_t)d * 8 + 4, v1);
}

__global__ void fold_w(const float* __restrict__ W2, const float* __restrict__ peWpe,
                       float* __restrict__ Wc) {
    int idx = blockIdx.x * blockDim.x + threadIdx.x;
    if (idx >= 64 * 128) return;
    int i = idx >> 7, j = idx & 127;
    float s = 0.0f;
    #pragma unroll 8
    for (int p = 0; p < 64; p++) s += W2[i * 64 + p] * peWpe[p * 128 + j];
    Wc[idx] = s;
}

__global__ void fold_b(const float* __restrict__ b2, const float* __restrict__ peWpe,
                       const float* __restrict__ peb, float* __restrict__ bc) {
    int j = threadIdx.x;
    float s = peb[j];
    #pragma unroll 8
    for (int p = 0; p < 64; p++) s += b2[p] * peWpe[p * 128 + j];
    bc[j] = s;
}

// WT[n][k] = fp16( k < Kl ? Wl[k][n] : Wr[k-Kl][n] )
__global__ void transpose_pack(const float* __restrict__ Wl, const float* __restrict__ Wr,
                               __half* __restrict__ WT, int Kl, int Kr) {
    int K = Kl + Kr;
    int idx = blockIdx.x * blockDim.x + threadIdx.x;
    if (idx >= 128 * K) return;
    int n = idx / K, k = idx % K;
    float w = (k < Kl) ? Wl[(size_t)k * 128 + n] : Wr[(size_t)(k - Kl) * 128 + n];
    WT[idx] = __float2half_rn(w);
}

__global__ void hid_kernel2(const float* __restrict__ agg,
                            const float* __restrict__ W1, const float* __restrict__ b1,
                            float* __restrict__ hid, int NTn) {
    __shared__ float sW1[2][512];
    __shared__ float sb1[2][64];
    int tid = threadIdx.x;
    for (int i = tid; i < 512; i += 256) { sW1[0][i] = W1[i]; sW1[1][i] = W1[512 + i]; }
    if (tid < 64) { sb1[0][tid] = b1[tid]; sb1[1][tid] = b1[64 + tid]; }
    __syncthreads();
    int r = tid >> 6, j = tid & 63;
    int row = blockIdx.x * 4 + r;
    if (row < NTn) {
        float a[8];
        #pragma unroll
        for (int k = 0; k < 8; k++) a[k] = agg[(size_t)row * 8 + k];
        #pragma unroll
        for (int l = 0; l < 2; l++) {
            float h = sb1[l][j];
            #pragma unroll
            for (int k = 0; k < 8; k++) h += a[k] * sW1[l][k * 64 + j];
            hid[(size_t)l * NT * 64 + (size_t)row * 64 + j] = fmaxf(h, 0.0f);
        }
    }
}

// ---------------- merged CSR mean gather (bf16 source): one warp per dst row ----------------
__global__ void mean_gather2(const __nv_bfloat16* __restrict__ lin16,
                             const int* __restrict__ csrBA, const int* __restrict__ offA,
                             const int* __restrict__ csrAB, const int* __restrict__ offB,
                             float* __restrict__ m)
{
    int w = (blockIdx.x * blockDim.x + threadIdx.x) >> 5;
    if (w >= NT) return;
    int lane = threadIdx.x & 31;
    const int* csr; const int* off; int srcBase, r;
    if (w < N_A) { csr = csrBA; off = offA; srcBase = N_A; r = w; }
    else         { csr = csrAB; off = offB; srcBase = 0;   r = w - N_A; }
    int s0 = off[r], s1 = off[r + 1];
    float4 acc = make_float4(0.f, 0.f, 0.f, 0.f);
    int i = s0;
    for (; i + 4 <= s1; i += 4) {
        int i0 = __ldg(csr + i),     i1 = __ldg(csr + i + 1);
        int i2 = __ldg(csr + i + 2), i3 = __ldg(csr + i + 3);
        #pragma unroll
        for (int u = 0; u < 4; u++) {
            int sidx = (u == 0) ? i0 : (u == 1) ? i1 : (u == 2) ? i2 : i3;
            uint2 pk = *(const uint2*)(lin16 + (size_t)(srcBase + sidx) * CC + lane * 4);
            __nv_bfloat162 h0 = *(__nv_bfloat162*)&pk.x;
            __nv_bfloat162 h1 = *(__nv_bfloat162*)&pk.y;
            float2 f0 = __bfloat1622float2(h0);
            float2 f1 = __bfloat1622float2(h1);
            acc.x += f0.x; acc.y += f0.y; acc.z += f1.x; acc.w += f1.y;
        }
    }
    for (; i < s1; i++) {
        int sidx = __ldg(csr + i);
        uint2 pk = *(const uint2*)(lin16 + (size_t)(srcBase + sidx) * CC + lane * 4);
        __nv_bfloat162 h0 = *(__nv_bfloat162*)&pk.x;
        __nv_bfloat162 h1 = *(__nv_bfloat162*)&pk.y;
        float2 f0 = __bfloat1622float2(h0);
        float2 f1 = __bfloat1622float2(h1);
        acc.x += f0.x; acc.y += f0.y; acc.z += f1.x; acc.w += f1.y;
    }
    float sc = 1.0f / (float)max(s1 - s0, 1);
    acc.x *= sc; acc.y *= sc; acc.z *= sc; acc.w *= sc;
    *(float4*)(m + (size_t)w * CC + lane * 4) = acc;
}

// ---------------- fp16 mma.sync GEMM (2-stage cp.async, merged A/B launch) ----------------
// A smem: fp32, 128 rows x 20-float stride (per K16 tile). B smem: fp16, 128 n-rows x 24-half stride.
#define A_TILE_F 2560                 // 128 * 20 floats
#define B_TILE_H 3072                 // 128 * 24 halfs (= 1536 floats)
#define GEMM_SMEM_F (640 + 2 * A_TILE_F + 2 * (B_TILE_H / 2))

__device__ __forceinline__ void load_tile(
    const float* __restrict__ X0, int K0, const float* __restrict__ X1, int K1,
    const __half* __restrict__ WT, int K, int m0, int M, int t,
    uint32_t asAddr, uint32_t bsAddr, int tid)
{
    int kb = t * 16;
    // A: 128 rows x 16 fp32, one float4 per thread x2
    #pragma unroll
    for (int i = 0; i < 2; i++) {
        int f = i * 256 + tid;
        int row = f >> 2, q = f & 3;
        int kk = kb + q * 4;
        bool pred = (m0 + row) < M;
        const float* src = (kk < K0)
            ? X0 + (size_t)(m0 + row) * K0 + kk
            : X1 + (size_t)(m0 + row) * K1 + (kk - K0);
        cpasync16(asAddr + (uint32_t)(row * 20 + q * 4) * 4, src, pred);
    }
    // B: 128 n-rows x 16 halfs, one 8-half (16B) chunk per thread
    {
        int n = tid >> 1, c = tid & 1;
        cpasync16(bsAddr + (uint32_t)(n * 24 + c * 8) * 2,
                  WT + (size_t)n * K + kb + c * 8, true);
    }
    CP_COMMIT();
}

template<bool DO_LN>
__global__ void __launch_bounds__(256, 2)
gemm_mma(const float* X0a, const float* X0b, int K0,
         const float* X1a, const float* X1b, int K1,
         const __half* WTa, const __half* WTb, int K,
         const float* biasA, const float* biasB,
         const float* gamA, const float* betA,
         const float* gamB, const float* betB,
         float* outA, float* outB, __nv_bfloat16* out16,
         int Ma, int Mb, int blocksA)
{
    extern __shared__ float sm[];
    float* s_bias  = sm;
    float* s_gamma = sm + 128;
    float* s_beta  = sm + 256;
    float* s_sum   = sm + 384;
    float* s_ss    = sm + 512;
    float* As      = sm + 640;
    __half* Bs     = (__half*)(sm + 640 + 2 * A_TILE_F);

    bool isB = (int)blockIdx.x >= blocksA;
    const float* X0   = isB ? X0b  : X0a;
    const float* X1   = isB ? X1b  : X1a;
    const __half* WT  = isB ? WTb  : WTa;
    const float* bias = isB ? biasB : biasA;
    const float* gamma = isB ? gamB : gamA;
    const float* beta  = isB ? betB : betA;
    float* out = isB ? outB : outA;
    int M  = isB ? Mb : Ma;
    int mrow0 = (isB ? ((int)blockIdx.x - blocksA) : (int)blockIdx.x) * 128;
    size_t row16base = isB ? (size_t)N_A : 0;

    int tid  = threadIdx.x;
    int lane = tid & 31;
    int warp = tid >> 5;
    int wm = warp & 3;
    int wn = warp >> 2;

    if (tid < 128) {
        s_bias[tid] = bias[tid];
        if (DO_LN) {
            s_gamma[tid] = gamma[tid];
            s_beta[tid]  = beta[tid];
            s_sum[tid] = 0.0f;
            s_ss[tid]  = 0.0f;
        }
    }

    uint32_t asAddr = smem_u32(As);
    uint32_t bsAddr = smem_u32(Bs);

    float c[2][8][4];
    #pragma unroll
    for (int mt = 0; mt < 2; mt++)
        #pragma unroll
        for (int nt = 0; nt < 8; nt++)
            #pragma unroll
            for (int j = 0; j < 4; j++) c[mt][nt][j] = 0.0f;

    const int T = K / 16;
    load_tile(X0, K0, X1, K1, WT, K, mrow0, M, 0, asAddr, bsAddr, tid);
    load_tile(X0, K0, X1, K1, WT, K, mrow0, M, 1,
              asAddr + A_TILE_F * 4, bsAddr + B_TILE_H * 2, tid);

    int kq = 2 * (lane & 3);      // A/B k-pair offset within the 16-K tile

    for (int t = 0; t < T; t++) {
        if (t + 1 < T) asm volatile("cp.async.wait_group 1;" ::: "memory");
        else           asm volatile("cp.async.wait_group 0;" ::: "memory");
        __syncthreads();

        const float* Ab = As + (t & 1) * A_TILE_F;
        const __half* Bb = Bs + (t & 1) * B_TILE_H;

        // A fragments (fp32 -> half2 in-register)
        uint32_t a[2][4];
        #pragma unroll
        for (int mt = 0; mt < 2; mt++) {
            int rb = wm * 32 + mt * 16 + (lane >> 2);
            a[mt][0] = pack_h2(*(const float2*)(Ab + rb * 20 + kq));
            a[mt][1] = pack_h2(*(const float2*)(Ab + (rb + 8) * 20 + kq));
            a[mt][2] = pack_h2(*(const float2*)(Ab + rb * 20 + kq + 8));
            a[mt][3] = pack_h2(*(const float2*)(Ab + (rb + 8) * 20 + kq + 8));
        }
        #pragma unroll
        for (int nt = 0; nt < 8; nt++) {
            int nb = wn * 64 + nt * 8 + (lane >> 2);
            uint32_t b0 = *(const uint32_t*)(Bb + nb * 24 + kq);
            uint32_t b1 = *(const uint32_t*)(Bb + nb * 24 + kq + 8);
            mma_f16(c[0][nt], a[0], b0, b1);
            mma_f16(c[1][nt], a[1], b0, b1);
        }
        __syncthreads();
        if (t + 2 < T)
            load_tile(X0, K0, X1, K1, WT, K, mrow0, M, t + 2,
                      asAddr + (uint32_t)(t & 1) * A_TILE_F * 4,
                      bsAddr + (uint32_t)(t & 1) * B_TILE_H * 2, tid);
    }

    // ---- add bias ----
    #pragma unroll
    for (int nt = 0; nt < 8; nt++) {
        int col = wn * 64 + nt * 8 + 2 * (lane & 3);
        float bx = s_bias[col], by = s_bias[col + 1];
        #pragma unroll
        for (int mt = 0; mt < 2; mt++) {
            c[mt][nt][0] += bx; c[mt][nt][1] += by;
            c[mt][nt][2] += bx; c[mt][nt][3] += by;
        }
    }

    if (!DO_LN) {
        #pragma unroll
        for (int mt = 0; mt < 2; mt++)
            #pragma unroll
            for (int h = 0; h < 2; h++) {
                int rloc = wm * 32 + mt * 16 + (lane >> 2) + h * 8;
                int row = mrow0 + rloc;
                if (row < M) {
                    #pragma unroll
                    for (int nt = 0; nt < 8; nt++) {
                        int col = wn * 64 + nt * 8 + 2 * (lane & 3);
                        float2 o = make_float2(c[mt][nt][h * 2], c[mt][nt][h * 2 + 1]);
                        *(float2*)(out + (size_t)row * 128 + col) = o;
                        __nv_bfloat162 o16 = __float22bfloat162_rn(o);
                        *(__nv_bfloat162*)(out16 + (row16base + row) * 128 + col) = o16;
                    }
                }
            }
        return;
    }

    // ---- LayerNorm + ReLU ----
    #pragma unroll
    for (int mt = 0; mt < 2; mt++)
        #pragma unroll
        for (int h = 0; h < 2; h++) {
            float s = 0.f, q = 0.f;
            #pragma unroll
            for (int nt = 0; nt < 8; nt++) {
                float v0 = c[mt][nt][h * 2], v1 = c[mt][nt][h * 2 + 1];
                s += v0 + v1;
                q += v0 * v0 + v1 * v1;
            }
            s += __shfl_xor_sync(0xffffffffu, s, 1);
            s += __shfl_xor_sync(0xffffffffu, s, 2);
            q += __shfl_xor_sync(0xffffffffu, q, 1);
            q += __shfl_xor_sync(0xffffffffu, q, 2);
            if ((lane & 3) == 0) {
                int rl = wm * 32 + mt * 16 + (lane >> 2) + h * 8;
                atomicAdd(&s_sum[rl], s);
                atomicAdd(&s_ss[rl], q);
            }
        }
    __syncthreads();
    #pragma unroll
    for (int mt = 0; mt < 2; mt++)
        #pragma unroll
        for (int h = 0; h < 2; h++) {
            int rl = wm * 32 + mt * 16 + (lane >> 2) + h * 8;
            int row = mrow0 + rl;
            float mu   = s_sum[rl] * (1.0f / 128.0f);
            float var  = s_ss[rl] * (1.0f / 128.0f) - mu * mu;
            float rstd = rsqrtf(var + 1e-5f);
            if (row < M) {
                #pragma unroll
                for (int nt = 0; nt < 8; nt++) {
                    int col = wn * 64 + nt * 8 + 2 * (lane & 3);
                    float2 o;
                    o.x = fmaxf((c[mt][nt][h * 2]     - mu) * rstd * s_gamma[col]     + s_beta[col],     0.f);
                    o.y = fmaxf((c[mt][nt][h * 2 + 1] - mu) * rstd * s_gamma[col + 1] + s_beta[col + 1], 0.f);
                    *(float2*)(out + (size_t)row * 128 + col) = o;
                }
            }
        }
}

// ---------------- launch ----------------
extern "C" void kernel_launch(void* const* d_in, const int* in_sizes, int n_in,
                              void* d_out, int out_size)
{
    const float* xA     = (const float*)d_in[0];
    const float* xB     = (const float*)d_in[1];
    const float* PE     = (const float*)d_in[2];
    const int*   edgeAB = (const int*)  d_in[3];
    const int*   edgeBA = (const int*)  d_in[4];
    const int*   hedge  = (const int*)  d_in[5];
    const float* sWl    = (const float*)d_in[6];
    const float* sbl    = (const float*)d_in[7];
    const float* sWr    = (const float*)d_in[8];
    const float* lng    = (const float*)d_in[9];
    const float* lnb    = (const float*)d_in[10];
    const float* pW1    = (const float*)d_in[11];
    const float* pb1    = (const float*)d_in[12];
    const float* pW2    = (const float*)d_in[13];
    const float* pb2    = (const float*)d_in[14];
    const float* peW    = (const float*)d_in[15];
    const float* peb    = (const float*)d_in[16];
    float* out = (float*)d_out;

    float *agg, *hid, *lin, *m, *cur, *Wc, *bc;
    __half *WTpe, *WTsage;
    __nv_bfloat16* lin16;
    int *cnt, *offA, *offB, *csrAB, *csrBA;
    cudaGetSymbolAddress((void**)&agg,    g_agg);
    cudaGetSymbolAddress((void**)&hid,    g_hid);
    cudaGetSymbolAddress((void**)&lin,    g_lin);
    cudaGetSymbolAddress((void**)&lin16,  g_lin16);
    cudaGetSymbolAddress((void**)&m,      g_m);
    cudaGetSymbolAddress((void**)&cur,    g_cur);
    cudaGetSymbolAddress((void**)&cnt,    g_cnt);
    cudaGetSymbolAddress((void**)&offA,   g_offA);
    cudaGetSymbolAddress((void**)&offB,   g_offB);
    cudaGetSymbolAddress((void**)&csrAB,  g_csrAB);
    cudaGetSymbolAddress((void**)&csrBA,  g_csrBA);
    cudaGetSymbolAddress((void**)&Wc,     g_Wc);
    cudaGetSymbolAddress((void**)&bc,     g_bc);
    cudaGetSymbolAddress((void**)&WTpe,   g_WTpe);
    cudaGetSymbolAddress((void**)&WTsage, g_WTsage);
    int* cntA = cnt;
    int* cntB = cnt + N_A;

    size_t gsm = GEMM_SMEM_F * sizeof(float);   // ~35 KB
    cudaFuncSetAttribute(gemm_mma<false>, cudaFuncAttributeMaxDynamicSharedMemorySize, (int)gsm);
    cudaFuncSetAttribute(gemm_mma<true>,  cudaFuncAttributeMaxDynamicSharedMemorySize, (int)gsm);

    cudaStream_t s2;
    cudaStreamCreateWithFlags(&s2, cudaStreamNonBlocking);
    cudaEvent_t e0, e_wt, e_csr;
    cudaEventCreateWithFlags(&e0,    cudaEventDisableTiming);
    cudaEventCreateWithFlags(&e_wt,  cudaEventDisableTiming);
    cudaEventCreateWithFlags(&e_csr, cudaEventDisableTiming);

    cudaEventRecord(e0, 0);
    cudaStreamWaitEvent(s2, e0, 0);

    // ---- s2: weight folds + transposes, then compact CSR chain ----
    for (int l = 0; l < 2; l++) {
        const float* peWpe = peW + (size_t)l * 192 * 128 + 128 * 128;
        fold_w<<<32, 256, 0, s2>>>(pW2 + l * 4096, peWpe, Wc + (size_t)l * 64 * 128);
        fold_b<<<1, 128, 0, s2>>>(pb2 + l * 64, peWpe, peb + l * 128, bc + l * 128);
        transpose_pack<<<(128 * 192 + 255) / 256, 256, 0, s2>>>(
            peW + (size_t)l * 192 * 128, Wc + (size_t)l * 64 * 128,
            WTpe + (size_t)l * 128 * 192, 128, 64);
        for (int e = 0; e < 2; e++) {
            int li = l * 2 + e;
            transpose_pack<<<(128 * 256 + 255) / 256, 256, 0, s2>>>(
                sWl + (size_t)li * 16384, sWr + (size_t)li * 16384,
                WTsage + (size_t)li * 128 * 256, 128, 128);
        }
    }
    cudaEventRecord(e_wt, s2);

    cudaMemsetAsync(cnt, 0, NT * sizeof(int), s2);
    count2<<<(2 * NE + 255) / 256, 256, 0, s2>>>(edgeAB + NE, edgeBA + NE, cntB, cntA);
    scan2<<<2, 1024, 0, s2>>>(cntA, offA, cntB, offB);
    fill2<<<(2 * NE + 255) / 256, 256, 0, s2>>>(edgeAB, edgeAB + NE, edgeBA, edgeBA + NE,
                                                cntB, cntA, csrAB, csrBA);
    cudaEventRecord(e_csr, s2);

    // ---- default stream: critical path ----
    cudaMemcpyAsync(agg, PE, (size_t)NT * 8 * sizeof(float), cudaMemcpyDeviceToDevice);
    agg_scatter<<<(EHN + 255) / 256, 256>>>(PE, hedge, hedge + EHN, agg, EHN);
    hid_kernel2<<<(NT + 3) / 4, 256>>>(agg, pW1, pb1, hid, NT);

    cudaStreamWaitEvent(0, e_wt, 0);

    const float* srcA = xA;
    const float* srcB = xB;
    const int blocksA = (N_A + 127) / 128;
    dim3 gGrid(2 * blocksA);
    float* linB = lin + (size_t)N_A * CC;
    float* mB   = m   + (size_t)N_A * CC;
    bool joined_csr = false;

    for (int l = 0; l < 2; l++) {
        const float* hl = hid + (size_t)l * NT * 64;

        gemm_mma<false><<<gGrid, 256, gsm>>>(
            srcA, srcB, 128,
            hl, hl + (size_t)N_A * 64, 64,
            WTpe + (size_t)l * 128 * 192, WTpe + (size_t)l * 128 * 192, 192,
            bc + l * 128, bc + l * 128,
            nullptr, nullptr, nullptr, nullptr,
            lin, linB, lin16, N_A, N_B, blocksA);

        if (!joined_csr) { cudaStreamWaitEvent(0, e_csr, 0); joined_csr = true; }

        mean_gather2<<<(NT * 32 + 255) / 256, 256>>>(lin16, csrBA, offA,
                                                     csrAB, offB, m);

        float* outA = (l == 1) ? out                    : cur;
        float* outB = (l == 1) ? out + (size_t)N_A * CC : cur + (size_t)N_A * CC;

        gemm_mma<true><<<gGrid, 256, gsm>>>(
            m, mB, 128,
            lin, linB, 128,
            WTsage + (size_t)(l * 2 + 1) * 128 * 256,
            WTsage + (size_t)(l * 2 + 0) * 128 * 256, 256,
            sbl + (l * 2 + 1) * 128, sbl + (l * 2 + 0) * 128,
            lng + (l * 2 + 0) * 128, lnb + (l * 2 + 0) * 128,
            lng + (l * 2 + 1) * 128, lnb + (l * 2 + 1) * 128,
            outA, outB, nullptr, N_A, N_B, blocksA);

        srcA = cur;
        srcB = cur + (size_t)N_A * CC;
    }
}

// round 13
// speedup vs baseline: 1.2690x; 1.0993x over previous
#include <cuda_runtime.h>
#include <cuda_bf16.h>
#include <cuda_fp16.h>
#include <math.h>
#include <stdint.h>

#define N_A 50000
#define N_B 50000
#define NT  100000
#define NE  800000
#define EHN 1600000
#define CC  128

// ---------------- device scratch (static, no allocation) ----------------
__device__ float  g_agg [NT * 8];
__device__ __half g_x16 [NT * CC];        // half copy of [xA | xB]
__device__ __half g_hid16[2 * NT * 64];   // relu(agg@W1+b1), half
__device__ __half g_lin16[NT * CC];       // pe-linear output, half
__device__ __half g_m16 [NT * CC];        // gathered means, half
__device__ __half g_cur16[NT * CC];       // layer output shadow, half
__device__ int    g_cnt [NT];             // [cntA | cntB]; reused as fill positions
__device__ int    g_offA[N_A + 1];
__device__ int    g_offB[N_B + 1];
__device__ int    g_csrAB[NE];            // src(A) ids grouped by dst(B)
__device__ int    g_csrBA[NE];            // src(B) ids grouped by dst(A)
__device__ float  g_Wc  [2 * 64 * 128];
__device__ float  g_bc  [2 * 128];
__device__ __half g_WTpe  [2 * 128 * 192];  // fp16 weights, [n][k]
__device__ __half g_WTsage[4 * 128 * 256];

// ---------------- helpers ----------------
__device__ __forceinline__ uint32_t smem_u32(const void* p) {
    uint32_t a;
    asm("{ .reg .u64 t; cvta.to.shared.u64 t, %1; cvt.u32.u64 %0, t; }" : "=r"(a) : "l"(p));
    return a;
}

__device__ __forceinline__ uint32_t pack_h2(float2 f) {
    __half2 h = __float22half2_rn(f);
    return *(uint32_t*)&h;
}

// fp16 HMMA m16n8k16, fp32 accumulate
__device__ __forceinline__ void mma_f16(float c[4], const uint32_t a[4],
                                        uint32_t b0, uint32_t b1) {
    asm volatile(
        "mma.sync.aligned.m16n8k16.row.col.f32.f16.f16.f32 "
        "{%0,%1,%2,%3}, {%4,%5,%6,%7}, {%8,%9}, {%0,%1,%2,%3};"
        : "+f"(c[0]), "+f"(c[1]), "+f"(c[2]), "+f"(c[3])
        : "r"(a[0]), "r"(a[1]), "r"(a[2]), "r"(a[3]), "r"(b0), "r"(b1));
}

__device__ __forceinline__ void cpasync16(uint32_t daddr, const void* g, bool pred) {
    int sz = pred ? 16 : 0;
    asm volatile("cp.async.cg.shared.global [%0], [%1], 16, %2;"
                 :: "r"(daddr), "l"(g), "r"(sz) : "memory");
}
#define CP_COMMIT() asm volatile("cp.async.commit_group;" ::: "memory")

__device__ __forceinline__ void red4(float* addr, float4 v) {
    asm volatile("red.global.add.v4.f32 [%0], {%1,%2,%3,%4};"
                 :: "l"(addr), "f"(v.x), "f"(v.y), "f"(v.z), "f"(v.w) : "memory");
}

// ---------------- graph preprocessing (merged two-direction kernels) ----------------
__global__ void count2(const int* __restrict__ dstAB, const int* __restrict__ dstBA,
                       int* __restrict__ cntB, int* __restrict__ cntA) {
    int e = blockIdx.x * blockDim.x + threadIdx.x;
    if (e < NE)            atomicAdd(&cntB[dstAB[e]], 1);
    else if (e < 2 * NE)   atomicAdd(&cntA[dstBA[e - NE]], 1);
}

__global__ void scan2(int* __restrict__ cntA, int* __restrict__ offA,
                      int* __restrict__ cntB, int* __restrict__ offB) {
    __shared__ int part[1024];
    int* cnt = blockIdx.x ? cntB : cntA;
    int* off = blockIdx.x ? offB : offA;
    const int N = N_A;                      // N_A == N_B
    int tid = threadIdx.x;
    int chunk = (N + 1023) >> 10;
    int start = tid * chunk;
    int end = min(start + chunk, N);
    int s = 0;
    for (int i = start; i < end; i++) s += cnt[i];
    part[tid] = s;
    __syncthreads();
    for (int o = 1; o < 1024; o <<= 1) {
        int t = (tid >= o) ? part[tid - o] : 0;
        __syncthreads();
        part[tid] += t;
        __syncthreads();
    }
    int pre = part[tid] - s;
    for (int i = start; i < end; i++) {
        int c = cnt[i];
        off[i] = pre;
        cnt[i] = pre;                       // becomes running fill position
        pre += c;
    }
    if (tid == 1023) off[N] = part[1023];
}

__global__ void fill2(const int* __restrict__ srcAB, const int* __restrict__ dstAB,
                      const int* __restrict__ srcBA, const int* __restrict__ dstBA,
                      int* __restrict__ posB, int* __restrict__ posA,
                      int* __restrict__ csrAB, int* __restrict__ csrBA) {
    int e = blockIdx.x * blockDim.x + threadIdx.x;
    if (e < NE) {
        int p = atomicAdd(&posB[dstAB[e]], 1);
        csrAB[p] = srcAB[e];
    } else if (e < 2 * NE) {
        int i = e - NE;
        int p = atomicAdd(&posA[dstBA[i]], 1);
        csrBA[p] = srcBA[i];
    }
}

__global__ void agg_scatter(const float* __restrict__ PE, const int* __restrict__ hsrc,
                            const int* __restrict__ hdst, float* __restrict__ agg, int E) {
    int e = blockIdx.x * blockDim.x + threadIdx.x;
    if (e >= E) return;
    int s = hsrc[e], d = hdst[e];
    float4 v0 = *(const float4*)(PE + (size_t)s * 8);
    float4 v1 = *(const float4*)(PE + (size_t)s * 8 + 4);
    red4(agg + (size_t)d * 8,     v0);
    red4(agg + (size_t)d * 8 + 4, v1);
}

__global__ void fold_w(const float* __restrict__ W2, const float* __restrict__ peWpe,
                       float* __restrict__ Wc) {
    int idx = blockIdx.x * blockDim.x + threadIdx.x;
    if (idx >= 64 * 128) return;
    int i = idx >> 7, j = idx & 127;
    float s = 0.0f;
    #pragma unroll 8
    for (int p = 0; p < 64; p++) s += W2[i * 64 + p] * peWpe[p * 128 + j];
    Wc[idx] = s;
}

__global__ void fold_b(const float* __restrict__ b2, const float* __restrict__ peWpe,
                       const float* __restrict__ peb, float* __restrict__ bc) {
    int j = threadIdx.x;
    float s = peb[j];
    #pragma unroll 8
    for (int p = 0; p < 64; p++) s += b2[p] * peWpe[p * 128 + j];
    bc[j] = s;
}

// WT[n][k] = fp16( k < Kl ? Wl[k][n] : Wr[k-Kl][n] )
__global__ void transpose_pack(const float* __restrict__ Wl, const float* __restrict__ Wr,
                               __half* __restrict__ WT, int Kl, int Kr) {
    int K = Kl + Kr;
    int idx = blockIdx.x * blockDim.x + threadIdx.x;
    if (idx >= 128 * K) return;
    int n = idx / K, k = idx % K;
    float w = (k < Kl) ? Wl[(size_t)k * 128 + n] : Wr[(size_t)(k - Kl) * 128 + n];
    WT[idx] = __float2half_rn(w);
}

// half copy of [xA | xB]
__global__ void conv_x16(const float* __restrict__ xA, const float* __restrict__ xB,
                         __half* __restrict__ x16) {
    int idx = blockIdx.x * blockDim.x + threadIdx.x;     // NT*CC/4 threads
    if (idx >= NT * CC / 4) return;
    size_t e = (size_t)idx * 4;
    size_t row = e >> 7;
    const float* src = (row < N_A) ? (xA + e) : (xB + (e - (size_t)N_A * CC));
    float4 v = *(const float4*)src;
    uint2 o;
    o.x = pack_h2(make_float2(v.x, v.y));
    o.y = pack_h2(make_float2(v.z, v.w));
    *(uint2*)(x16 + e) = o;
}

__global__ void hid_kernel2(const float* __restrict__ agg,
                            const float* __restrict__ W1, const float* __restrict__ b1,
                            __half* __restrict__ hid, int NTn) {
    __shared__ float sW1[2][512];
    __shared__ float sb1[2][64];
    int tid = threadIdx.x;
    for (int i = tid; i < 512; i += 256) { sW1[0][i] = W1[i]; sW1[1][i] = W1[512 + i]; }
    if (tid < 64) { sb1[0][tid] = b1[tid]; sb1[1][tid] = b1[64 + tid]; }
    __syncthreads();
    int r = tid >> 6, j = tid & 63;
    int row = blockIdx.x * 4 + r;
    if (row < NTn) {
        float a[8];
        #pragma unroll
        for (int k = 0; k < 8; k++) a[k] = agg[(size_t)row * 8 + k];
        #pragma unroll
        for (int l = 0; l < 2; l++) {
            float h = sb1[l][j];
            #pragma unroll
            for (int k = 0; k < 8; k++) h += a[k] * sW1[l][k * 64 + j];
            hid[(size_t)l * NT * 64 + (size_t)row * 64 + j] = __float2half_rn(fmaxf(h, 0.0f));
        }
    }
}

// ---------------- merged CSR mean gather (half in, half out): one warp per dst row ------
__global__ void mean_gather2(const __half* __restrict__ lin16,
                             const int* __restrict__ csrBA, const int* __restrict__ offA,
                             const int* __restrict__ csrAB, const int* __restrict__ offB,
                             __half* __restrict__ m16)
{
    int w = (blockIdx.x * blockDim.x + threadIdx.x) >> 5;
    if (w >= NT) return;
    int lane = threadIdx.x & 31;
    const int* csr; const int* off; int srcBase, r;
    if (w < N_A) { csr = csrBA; off = offA; srcBase = N_A; r = w; }
    else         { csr = csrAB; off = offB; srcBase = 0;   r = w - N_A; }
    int s0 = off[r], s1 = off[r + 1];
    float4 acc = make_float4(0.f, 0.f, 0.f, 0.f);
    int i = s0;
    for (; i + 4 <= s1; i += 4) {
        int i0 = __ldg(csr + i),     i1 = __ldg(csr + i + 1);
        int i2 = __ldg(csr + i + 2), i3 = __ldg(csr + i + 3);
        #pragma unroll
        for (int u = 0; u < 4; u++) {
            int sidx = (u == 0) ? i0 : (u == 1) ? i1 : (u == 2) ? i2 : i3;
            uint2 pk = *(const uint2*)(lin16 + (size_t)(srcBase + sidx) * CC + lane * 4);
            __half2 h0 = *(__half2*)&pk.x;
            __half2 h1 = *(__half2*)&pk.y;
            float2 f0 = __half22float2(h0);
            float2 f1 = __half22float2(h1);
            acc.x += f0.x; acc.y += f0.y; acc.z += f1.x; acc.w += f1.y;
        }
    }
    for (; i < s1; i++) {
        int sidx = __ldg(csr + i);
        uint2 pk = *(const uint2*)(lin16 + (size_t)(srcBase + sidx) * CC + lane * 4);
        __half2 h0 = *(__half2*)&pk.x;
        __half2 h1 = *(__half2*)&pk.y;
        float2 f0 = __half22float2(h0);
        float2 f1 = __half22float2(h1);
        acc.x += f0.x; acc.y += f0.y; acc.z += f1.x; acc.w += f1.y;
    }
    float sc = 1.0f / (float)max(s1 - s0, 1);
    uint2 o;
    o.x = pack_h2(make_float2(acc.x * sc, acc.y * sc));
    o.y = pack_h2(make_float2(acc.z * sc, acc.w * sc));
    *(uint2*)(m16 + (size_t)w * CC + lane * 4) = o;
}

// ---------------- fp16 mma.sync GEMM (2-stage cp.async, merged A/B launch) ----------------
// A smem: fp16, 128 rows x 24-half stride. B smem: fp16, 128 n-rows x 24-half stride.
#define T_TILE_H 3072                 // 128 * 24 halfs per tile buffer
#define GEMM_SMEM_F (640 + 4 * (T_TILE_H / 2))

__device__ __forceinline__ void load_tile(
    const __half* __restrict__ X0, int K0, const __half* __restrict__ X1, int K1,
    const __half* __restrict__ WT, int K, int m0, int M, int t,
    uint32_t asAddr, uint32_t bsAddr, int tid)
{
    int kb = t * 16;
    // A: 128 rows x 16 halfs, one 8-half (16B) chunk per thread
    {
        int row = tid >> 1, c = tid & 1;
        int kk = kb + c * 8;
        bool pred = (m0 + row) < M;
        const __half* src = (kk < K0)
            ? X0 + (size_t)(m0 + row) * K0 + kk
            : X1 + (size_t)(m0 + row) * K1 + (kk - K0);
        cpasync16(asAddr + (uint32_t)(row * 24 + c * 8) * 2, src, pred);
    }
    // B: 128 n-rows x 16 halfs, one 8-half chunk per thread
    {
        int n = tid >> 1, c = tid & 1;
        cpasync16(bsAddr + (uint32_t)(n * 24 + c * 8) * 2,
                  WT + (size_t)n * K + kb + c * 8, true);
    }
    CP_COMMIT();
}

template<bool DO_LN>
__global__ void __launch_bounds__(256, 2)
gemm_mma(const __half* X0a, const __half* X0b, int K0,
         const __half* X1a, const __half* X1b, int K1,
         const __half* WTa, const __half* WTb, int K,
         const float* biasA, const float* biasB,
         const float* gamA, const float* betA,
         const float* gamB, const float* betB,
         float* outA, float* outB, __half* out16,
         int Ma, int Mb, int blocksA)
{
    extern __shared__ float sm[];
    float* s_bias  = sm;
    float* s_gamma = sm + 128;
    float* s_beta  = sm + 256;
    float* s_sum   = sm + 384;
    float* s_ss    = sm + 512;
    __half* As     = (__half*)(sm + 640);
    __half* Bs     = As + 2 * T_TILE_H;

    bool isB = (int)blockIdx.x >= blocksA;
    const __half* X0  = isB ? X0b  : X0a;
    const __half* X1  = isB ? X1b  : X1a;
    const __half* WT  = isB ? WTb  : WTa;
    const float* bias = isB ? biasB : biasA;
    const float* gamma = isB ? gamB : gamA;
    const float* beta  = isB ? betB : betA;
    float* out = isB ? outB : outA;
    int M  = isB ? Mb : Ma;
    int mrow0 = (isB ? ((int)blockIdx.x - blocksA) : (int)blockIdx.x) * 128;
    size_t row16base = isB ? (size_t)N_A : 0;

    int tid  = threadIdx.x;
    int lane = tid & 31;
    int warp = tid >> 5;
    int wm = warp & 3;
    int wn = warp >> 2;

    if (tid < 128) {
        s_bias[tid] = bias[tid];
        if (DO_LN) {
            s_gamma[tid] = gamma[tid];
            s_beta[tid]  = beta[tid];
            s_sum[tid] = 0.0f;
            s_ss[tid]  = 0.0f;
        }
    }

    uint32_t asAddr = smem_u32(As);
    uint32_t bsAddr = smem_u32(Bs);

    float c[2][8][4];
    #pragma unroll
    for (int mt = 0; mt < 2; mt++)
        #pragma unroll
        for (int nt = 0; nt < 8; nt++)
            #pragma unroll
            for (int j = 0; j < 4; j++) c[mt][nt][j] = 0.0f;

    const int T = K / 16;
    load_tile(X0, K0, X1, K1, WT, K, mrow0, M, 0, asAddr, bsAddr, tid);
    load_tile(X0, K0, X1, K1, WT, K, mrow0, M, 1,
              asAddr + T_TILE_H * 2, bsAddr + T_TILE_H * 2, tid);

    int kq = 2 * (lane & 3);      // k-pair offset within the 16-K tile

    for (int t = 0; t < T; t++) {
        if (t + 1 < T) asm volatile("cp.async.wait_group 1;" ::: "memory");
        else           asm volatile("cp.async.wait_group 0;" ::: "memory");
        __syncthreads();

        const __half* Ab = As + (t & 1) * T_TILE_H;
        const __half* Bb = Bs + (t & 1) * T_TILE_H;

        uint32_t a[2][4];
        #pragma unroll
        for (int mt = 0; mt < 2; mt++) {
            int rb = wm * 32 + mt * 16 + (lane >> 2);
            a[mt][0] = *(const uint32_t*)(Ab + rb * 24 + kq);
            a[mt][1] = *(const uint32_t*)(Ab + (rb + 8) * 24 + kq);
            a[mt][2] = *(const uint32_t*)(Ab + rb * 24 + kq + 8);
            a[mt][3] = *(const uint32_t*)(Ab + (rb + 8) * 24 + kq + 8);
        }
        #pragma unroll
        for (int nt = 0; nt < 8; nt++) {
            int nb = wn * 64 + nt * 8 + (lane >> 2);
            uint32_t b0 = *(const uint32_t*)(Bb + nb * 24 + kq);
            uint32_t b1 = *(const uint32_t*)(Bb + nb * 24 + kq + 8);
            mma_f16(c[0][nt], a[0], b0, b1);
            mma_f16(c[1][nt], a[1], b0, b1);
        }
        __syncthreads();
        if (t + 2 < T)
            load_tile(X0, K0, X1, K1, WT, K, mrow0, M, t + 2,
                      asAddr + (uint32_t)(t & 1) * T_TILE_H * 2,
                      bsAddr + (uint32_t)(t & 1) * T_TILE_H * 2, tid);
    }

    // ---- add bias ----
    #pragma unroll
    for (int nt = 0; nt < 8; nt++) {
        int col = wn * 64 + nt * 8 + 2 * (lane & 3);
        float bx = s_bias[col], by = s_bias[col + 1];
        #pragma unroll
        for (int mt = 0; mt < 2; mt++) {
            c[mt][nt][0] += bx; c[mt][nt][1] += by;
            c[mt][nt][2] += bx; c[mt][nt][3] += by;
        }
    }

    if (!DO_LN) {
        // write half shadow only (lin16)
        #pragma unroll
        for (int mt = 0; mt < 2; mt++)
            #pragma unroll
            for (int h = 0; h < 2; h++) {
                int rloc = wm * 32 + mt * 16 + (lane >> 2) + h * 8;
                int row = mrow0 + rloc;
                if (row < M) {
                    #pragma unroll
                    for (int nt = 0; nt < 8; nt++) {
                        int col = wn * 64 + nt * 8 + 2 * (lane & 3);
                        uint32_t o16 = pack_h2(make_float2(c[mt][nt][h * 2], c[mt][nt][h * 2 + 1]));
                        *(uint32_t*)(out16 + (row16base + row) * 128 + col) = o16;
                    }
                }
            }
        return;
    }

    // ---- LayerNorm + ReLU ----
    #pragma unroll
    for (int mt = 0; mt < 2; mt++)
        #pragma unroll
        for (int h = 0; h < 2; h++) {
            float s = 0.f, q = 0.f;
            #pragma unroll
            for (int nt = 0; nt < 8; nt++) {
                float v0 = c[mt][nt][h * 2], v1 = c[mt][nt][h * 2 + 1];
                s += v0 + v1;
                q += v0 * v0 + v1 * v1;
            }
            s += __shfl_xor_sync(0xffffffffu, s, 1);
            s += __shfl_xor_sync(0xffffffffu, s, 2);
            q += __shfl_xor_sync(0xffffffffu, q, 1);
            q += __shfl_xor_sync(0xffffffffu, q, 2);
            if ((lane & 3) == 0) {
                int rl = wm * 32 + mt * 16 + (lane >> 2) + h * 8;
                atomicAdd(&s_sum[rl], s);
                atomicAdd(&s_ss[rl], q);
            }
        }
    __syncthreads();
    #pragma unroll
    for (int mt = 0; mt < 2; mt++)
        #pragma unroll
        for (int h = 0; h < 2; h++) {
            int rl = wm * 32 + mt * 16 + (lane >> 2) + h * 8;
            int row = mrow0 + rl;
            float mu   = s_sum[rl] * (1.0f / 128.0f);
            float var  = s_ss[rl] * (1.0f / 128.0f) - mu * mu;
            float rstd = rsqrtf(var + 1e-5f);
            if (row < M) {
                #pragma unroll
                for (int nt = 0; nt < 8; nt++) {
                    int col = wn * 64 + nt * 8 + 2 * (lane & 3);
                    float2 o;
                    o.x = fmaxf((c[mt][nt][h * 2]     - mu) * rstd * s_gamma[col]     + s_beta[col],     0.f);
                    o.y = fmaxf((c[mt][nt][h * 2 + 1] - mu) * rstd * s_gamma[col + 1] + s_beta[col + 1], 0.f);
                    if (out)
                        *(float2*)(out + (size_t)row * 128 + col) = o;
                    if (out16)
                        *(uint32_t*)(out16 + (row16base + row) * 128 + col) = pack_h2(o);
                }
            }
        }
}

// ---------------- launch ----------------
extern "C" void kernel_launch(void* const* d_in, const int* in_sizes, int n_in,
                              void* d_out, int out_size)
{
    const float* xA     = (const float*)d_in[0];
    const float* xB     = (const float*)d_in[1];
    const float* PE     = (const float*)d_in[2];
    const int*   edgeAB = (const int*)  d_in[3];
    const int*   edgeBA = (const int*)  d_in[4];
    const int*   hedge  = (const int*)  d_in[5];
    const float* sWl    = (const float*)d_in[6];
    const float* sbl    = (const float*)d_in[7];
    const float* sWr    = (const float*)d_in[8];
    const float* lng    = (const float*)d_in[9];
    const float* lnb    = (const float*)d_in[10];
    const float* pW1    = (const float*)d_in[11];
    const float* pb1    = (const float*)d_in[12];
    const float* pW2    = (const float*)d_in[13];
    const float* pb2    = (const float*)d_in[14];
    const float* peW    = (const float*)d_in[15];
    const float* peb    = (const float*)d_in[16];
    float* out = (float*)d_out;

    float *agg, *Wc, *bc;
    __half *x16, *hid16, *lin16, *m16, *cur16, *WTpe, *WTsage;
    int *cnt, *offA, *offB, *csrAB, *csrBA;
    cudaGetSymbolAddress((void**)&agg,    g_agg);
    cudaGetSymbolAddress((void**)&x16,    g_x16);
    cudaGetSymbolAddress((void**)&hid16,  g_hid16);
    cudaGetSymbolAddress((void**)&lin16,  g_lin16);
    cudaGetSymbolAddress((void**)&m16,    g_m16);
    cudaGetSymbolAddress((void**)&cur16,  g_cur16);
    cudaGetSymbolAddress((void**)&cnt,    g_cnt);
    cudaGetSymbolAddress((void**)&offA,   g_offA);
    cudaGetSymbolAddress((void**)&offB,   g_offB);
    cudaGetSymbolAddress((void**)&csrAB,  g_csrAB);
    cudaGetSymbolAddress((void**)&csrBA,  g_csrBA);
    cudaGetSymbolAddress((void**)&Wc,     g_Wc);
    cudaGetSymbolAddress((void**)&bc,     g_bc);
    cudaGetSymbolAddress((void**)&WTpe,   g_WTpe);
    cudaGetSymbolAddress((void**)&WTsage, g_WTsage);
    int* cntA = cnt;
    int* cntB = cnt + N_A;

    size_t gsm = GEMM_SMEM_F * sizeof(float);   // ~27 KB
    cudaFuncSetAttribute(gemm_mma<false>, cudaFuncAttributeMaxDynamicSharedMemorySize, (int)gsm);
    cudaFuncSetAttribute(gemm_mma<true>,  cudaFuncAttributeMaxDynamicSharedMemorySize, (int)gsm);

    cudaStream_t s2;
    cudaStreamCreateWithFlags(&s2, cudaStreamNonBlocking);
    cudaEvent_t e0, e_wt, e_csr;
    cudaEventCreateWithFlags(&e0,    cudaEventDisableTiming);
    cudaEventCreateWithFlags(&e_wt,  cudaEventDisableTiming);
    cudaEventCreateWithFlags(&e_csr, cudaEventDisableTiming);

    cudaEventRecord(e0, 0);
    cudaStreamWaitEvent(s2, e0, 0);

    // ---- s2: x16 conversion + weight folds/transposes, then compact CSR chain ----
    conv_x16<<<(NT * CC / 4 + 255) / 256, 256, 0, s2>>>(xA, xB, x16);
    for (int l = 0; l < 2; l++) {
        const float* peWpe = peW + (size_t)l * 192 * 128 + 128 * 128;
        fold_w<<<32, 256, 0, s2>>>(pW2 + l * 4096, peWpe, Wc + (size_t)l * 64 * 128);
        fold_b<<<1, 128, 0, s2>>>(pb2 + l * 64, peWpe, peb + l * 128, bc + l * 128);
        transpose_pack<<<(128 * 192 + 255) / 256, 256, 0, s2>>>(
            peW + (size_t)l * 192 * 128, Wc + (size_t)l * 64 * 128,
            WTpe + (size_t)l * 128 * 192, 128, 64);
        for (int e = 0; e < 2; e++) {
            int li = l * 2 + e;
            transpose_pack<<<(128 * 256 + 255) / 256, 256, 0, s2>>>(
                sWl + (size_t)li * 16384, sWr + (size_t)li * 16384,
                WTsage + (size_t)li * 128 * 256, 128, 128);
        }
    }
    cudaEventRecord(e_wt, s2);

    cudaMemsetAsync(cnt, 0, NT * sizeof(int), s2);
    count2<<<(2 * NE + 255) / 256, 256, 0, s2>>>(edgeAB + NE, edgeBA + NE, cntB, cntA);
    scan2<<<2, 1024, 0, s2>>>(cntA, offA, cntB, offB);
    fill2<<<(2 * NE + 255) / 256, 256, 0, s2>>>(edgeAB, edgeAB + NE, edgeBA, edgeBA + NE,
                                                cntB, cntA, csrAB, csrBA);
    cudaEventRecord(e_csr, s2);

    // ---- default stream: critical path ----
    cudaMemcpyAsync(agg, PE, (size_t)NT * 8 * sizeof(float), cudaMemcpyDeviceToDevice);
    agg_scatter<<<(EHN + 255) / 256, 256>>>(PE, hedge, hedge + EHN, agg, EHN);
    hid_kernel2<<<(NT + 3) / 4, 256>>>(agg, pW1, pb1, hid16, NT);

    cudaStreamWaitEvent(0, e_wt, 0);

    const __half* srcA = x16;
    const __half* srcB = x16 + (size_t)N_A * CC;
    const int blocksA = (N_A + 127) / 128;
    dim3 gGrid(2 * blocksA);
    bool joined_csr = false;

    for (int l = 0; l < 2; l++) {
        const __half* hl = hid16 + (size_t)l * NT * 64;

        // pe-linear (phi layer-2 folded): lin16 = half([x | relu(h)] @ WTpe^T + bc)
        gemm_mma<false><<<gGrid, 256, gsm>>>(
            srcA, srcB, 128,
            hl, hl + (size_t)N_A * 64, 64,
            WTpe + (size_t)l * 128 * 192, WTpe + (size_t)l * 128 * 192, 192,
            bc + l * 128, bc + l * 128,
            nullptr, nullptr, nullptr, nullptr,
            nullptr, nullptr, lin16, N_A, N_B, blocksA);

        if (!joined_csr) { cudaStreamWaitEvent(0, e_csr, 0); joined_csr = true; }

        mean_gather2<<<(NT * 32 + 255) / 256, 256>>>(lin16, csrBA, offA,
                                                     csrAB, offB, m16);

        float* outA = (l == 1) ? out                    : nullptr;
        float* outB = (l == 1) ? out + (size_t)N_A * CC : nullptr;
        __half* o16 = (l == 0) ? cur16 : nullptr;

        // SAGE + LN + ReLU (K = 256). Weight idx0 -> B-update, idx1 -> A-update.
        gemm_mma<true><<<gGrid, 256, gsm>>>(
            m16, m16 + (size_t)N_A * CC, 128,
            lin16, lin16 + (size_t)N_A * CC, 128,
            WTsage + (size_t)(l * 2 + 1) * 128 * 256,
            WTsage + (size_t)(l * 2 + 0) * 128 * 256, 256,
            sbl + (l * 2 + 1) * 128, sbl + (l * 2 + 0) * 128,
            lng + (l * 2 + 0) * 128, lnb + (l * 2 + 0) * 128,
            lng + (l * 2 + 1) * 128, lnb + (l * 2 + 1) * 128,
            outA, outB, o16, N_A, N_B, blocksA);

        srcA = cur16;
        srcB = cur16 + (size_t)N_A * CC;
    }
}